// round 5
// baseline (speedup 1.0000x reference)
#include <cuda_runtime.h>
#include <cuda_bf16.h>
#include <mma.h>
#include <cstdint>

using namespace nvcuda;

#define SD 512
#define NB 512
#define SCALE 0.044194173824159216f
#define LDA 24          // bf16 tile row stride (48B = 3*16B, conflict-free LDSM)
#define LDB 136         // k2 V-tile row stride (272B = 17*16B)
#define LDCS 132        // fp32 staging stride (multiple of 4 for wmma store)
#define K1_SMEM (128 * 132 * 4)   // 67584: Cs staging, aliases the mainloop tiles

// ---- scratch (device globals; no allocation) ----
__device__ __nv_bfloat16 g_E[(size_t)NB * SD * SD];   // exp(scale*QK^T), unnormalized
__device__ float g_partZ[NB][4][SD];
__device__ float g_Zinv[NB][SD];

__device__ __forceinline__ uint2 pack4(float4 v) {
    __nv_bfloat162 a = __float22bfloat162_rn(make_float2(v.x, v.y));
    __nv_bfloat162 b = __float22bfloat162_rn(make_float2(v.z, v.w));
    uint2 u;
    u.x = *(uint32_t*)&a;
    u.y = *(uint32_t*)&b;
    return u;
}

// ---------------------------------------------------------------------------
// k1: S = Q K^T (bf16 HMMA, fp32 acc), E = exp(scale*S) -> gmem, col partials.
// CTA: 128 threads = 4 warps (2x2), warp tile 64x64, CTA tile 128x128, BK=16.
// grid (16, 512): blockIdx.x = it*4 + nt.
// dyn smem: tiles As(buf) @ buf*6144, Bs(buf) @ 12288 + buf*6144 (24KB),
//           aliased after mainloop by Cs fp32 [128][132] (67584B).
// ---------------------------------------------------------------------------
__global__ void __launch_bounds__(128) k1_qk(const float* __restrict__ Q,
                                             const float* __restrict__ Km)
{
    extern __shared__ char sm[];
    float* Cs = (float*)sm;

    const int batch = blockIdx.y, it = blockIdx.x >> 2, nt = blockIdx.x & 3;
    const float* Qb = Q  + ((size_t)batch * SD + it * 128) * SD;
    const float* Kb = Km + ((size_t)batch * SD + nt * 128) * SD;

    const int t = threadIdx.x, wid = t >> 5;
    const int wr = wid & 1, wc = wid >> 1;
    const int lr = t >> 2;           // 0..31
    const int lq = (t & 3) * 4;      // 0,4,8,12 (float col within 16-wide chunk)

    wmma::fragment<wmma::accumulator, 16, 16, 16, float> acc[4][4];
#pragma unroll
    for (int i = 0; i < 4; i++)
#pragma unroll
        for (int j = 0; j < 4; j++) wmma::fill_fragment(acc[i][j], 0.0f);

    float4 ra[4], rb[4];

    // prologue: load + store chunk 0
#pragma unroll
    for (int p = 0; p < 4; p++) {
        const int r = lr + p * 32;
        ra[p] = *(const float4*)(Qb + (size_t)r * SD + lq);
        rb[p] = *(const float4*)(Kb + (size_t)r * SD + lq);
    }
    {
        __nv_bfloat16* As = (__nv_bfloat16*)(sm);
        __nv_bfloat16* Bs = (__nv_bfloat16*)(sm + 12288);
#pragma unroll
        for (int p = 0; p < 4; p++) {
            const int r = lr + p * 32;
            *(uint2*)(As + r * LDA + lq) = pack4(ra[p]);
            *(uint2*)(Bs + r * LDA + lq) = pack4(rb[p]);
        }
    }
    __syncthreads();

#pragma unroll 1
    for (int c = 0; c < 32; c++) {
        const int buf = c & 1;
        if (c < 31) {
            const int kk = (c + 1) * 16;
#pragma unroll
            for (int p = 0; p < 4; p++) {
                const int r = lr + p * 32;
                ra[p] = *(const float4*)(Qb + (size_t)r * SD + kk + lq);
                rb[p] = *(const float4*)(Kb + (size_t)r * SD + kk + lq);
            }
        }
        const __nv_bfloat16* As = (const __nv_bfloat16*)(sm + buf * 6144);
        const __nv_bfloat16* Bs = (const __nv_bfloat16*)(sm + 12288 + buf * 6144);

        wmma::fragment<wmma::matrix_a, 16, 16, 16, __nv_bfloat16, wmma::row_major> af[4];
        wmma::fragment<wmma::matrix_b, 16, 16, 16, __nv_bfloat16, wmma::col_major> bf[4];
#pragma unroll
        for (int i = 0; i < 4; i++)
            wmma::load_matrix_sync(af[i], As + (wr * 64 + i * 16) * LDA, LDA);
#pragma unroll
        for (int j = 0; j < 4; j++)
            wmma::load_matrix_sync(bf[j], Bs + (wc * 64 + j * 16) * LDA, LDA);
#pragma unroll
        for (int i = 0; i < 4; i++)
#pragma unroll
            for (int j = 0; j < 4; j++)
                wmma::mma_sync(acc[i][j], af[i], bf[j], acc[i][j]);

        if (c < 31) {
            __nv_bfloat16* Ad = (__nv_bfloat16*)(sm + (buf ^ 1) * 6144);
            __nv_bfloat16* Bd = (__nv_bfloat16*)(sm + 12288 + (buf ^ 1) * 6144);
#pragma unroll
            for (int p = 0; p < 4; p++) {
                const int r = lr + p * 32;
                *(uint2*)(Ad + r * LDA + lq) = pack4(ra[p]);
                *(uint2*)(Bd + r * LDA + lq) = pack4(rb[p]);
            }
        }
        __syncthreads();
    }

    // exp in registers (elementwise on accumulators — layout independent)
#pragma unroll
    for (int i = 0; i < 4; i++)
#pragma unroll
        for (int j = 0; j < 4; j++)
#pragma unroll
            for (int e = 0; e < acc[i][j].num_elements; e++)
                acc[i][j].x[e] = __expf(acc[i][j].x[e] * SCALE);

    // stage exp'd tile to smem (tiles fully consumed; alias is safe post-sync)
#pragma unroll
    for (int i = 0; i < 4; i++)
#pragma unroll
        for (int j = 0; j < 4; j++)
            wmma::store_matrix_sync(Cs + (wr * 64 + i * 16) * LDCS + wc * 64 + j * 16,
                                    acc[i][j], LDCS, wmma::mem_row_major);
    __syncthreads();

    // deterministic column sums: thread t owns column t (conflict-free banks)
    {
        float z = 0.0f;
#pragma unroll 8
        for (int r = 0; r < 128; r++) z += Cs[r * LDCS + t];
        g_partZ[batch][it][nt * 128 + t] = z;
    }

    // pack E (bf16), coalesced: 4 lanes cover 256B per row
    __nv_bfloat16* Eb = g_E + ((size_t)batch * SD + it * 128) * SD + nt * 128;
#pragma unroll
    for (int p = 0; p < 4; p++) {
        const int r = (t >> 2) + p * 32;
        const int c0 = (t & 3) * 32;
        const float* src = Cs + r * LDCS + c0;
#pragma unroll
        for (int q = 0; q < 4; q++) {
            uint2 lo = pack4(*(const float4*)(src + q * 8));
            uint2 hi = pack4(*(const float4*)(src + q * 8 + 4));
            uint4 o; o.x = lo.x; o.y = lo.y; o.z = hi.x; o.w = hi.y;
            *(uint4*)(Eb + (size_t)r * SD + c0 + q * 8) = o;
        }
    }
}

// ---------------------------------------------------------------------------
// k_zred: Z = fixed-order sum of 4 partials; store 1/Z fp32
// ---------------------------------------------------------------------------
__global__ void __launch_bounds__(512) k_zred()
{
    const int b = blockIdx.x, c = threadIdx.x;
    float z = g_partZ[b][0][c] + g_partZ[b][1][c] + g_partZ[b][2][c] + g_partZ[b][3][c];
    g_Zinv[b][c] = 1.0f / z;
}

// ---------------------------------------------------------------------------
// k2: out = E @ (diag(1/Z) V). A = E bf16 (gmem scratch), B = V fp32 scaled by
// zinv[k] at load -> bf16. Accumulators stored directly to gmem (no staging).
// CTA: 128 threads, 4 warps 2x2, 64x64 warp tiles, BK=16 double-buffered.
// ---------------------------------------------------------------------------
__global__ void __launch_bounds__(128) k2_pv(const float* __restrict__ V,
                                             float* __restrict__ O)
{
    __shared__ __nv_bfloat16 As[2][128 * LDA];
    __shared__ __nv_bfloat16 Bs[2][16 * LDB];
    __shared__ float zs[SD];

    const int batch = blockIdx.y, it = blockIdx.x >> 2, jt = blockIdx.x & 3;
    const __nv_bfloat16* Eb = g_E + ((size_t)batch * SD + it * 128) * SD;
    const float* Vb = V + (size_t)batch * SD * SD + jt * 128;

    const int t = threadIdx.x, wid = t >> 5;
    const int wr = wid & 1, wc = wid >> 1;

    ((float4*)zs)[t] = ((const float4*)g_Zinv[batch])[t];   // 128*4 = 512 floats

    wmma::fragment<wmma::accumulator, 16, 16, 16, float> acc[4][4];
#pragma unroll
    for (int i = 0; i < 4; i++)
#pragma unroll
        for (int j = 0; j < 4; j++) wmma::fill_fragment(acc[i][j], 0.0f);

    uint4 ea[2];
    float4 rv[4];

    // prologue chunk 0 (E loads don't need zs; V scaling reads zs after sync)
#pragma unroll
    for (int h = 0; h < 2; h++) {
        const int u = t + 128 * h;
        ea[h] = *(const uint4*)(Eb + (size_t)(u >> 1) * SD + (u & 1) * 8);
    }
#pragma unroll
    for (int p = 0; p < 4; p++) {
        const int u = t + 128 * p;
        rv[p] = *(const float4*)(Vb + (size_t)(u >> 5) * SD + (u & 31) * 4);
    }
    __syncthreads();   // zs ready
    {
#pragma unroll
        for (int h = 0; h < 2; h++) {
            const int u = t + 128 * h;
            *(uint4*)(&As[0][(u >> 1) * LDA + (u & 1) * 8]) = ea[h];
        }
#pragma unroll
        for (int p = 0; p < 4; p++) {
            const int u = t + 128 * p;
            const int r = u >> 5;
            const float zi = zs[r];
            float4 v = rv[p];
            v.x *= zi; v.y *= zi; v.z *= zi; v.w *= zi;
            *(uint2*)(&Bs[0][r * LDB + (u & 31) * 4]) = pack4(v);
        }
    }
    __syncthreads();

#pragma unroll 1
    for (int c = 0; c < 32; c++) {
        const int buf = c & 1;
        const int kk1 = (c + 1) * 16;
        if (c < 31) {
#pragma unroll
            for (int h = 0; h < 2; h++) {
                const int u = t + 128 * h;
                ea[h] = *(const uint4*)(Eb + (size_t)(u >> 1) * SD + kk1 + (u & 1) * 8);
            }
#pragma unroll
            for (int p = 0; p < 4; p++) {
                const int u = t + 128 * p;
                rv[p] = *(const float4*)(Vb + (size_t)(kk1 + (u >> 5)) * SD + (u & 31) * 4);
            }
        }

        wmma::fragment<wmma::matrix_a, 16, 16, 16, __nv_bfloat16, wmma::row_major> af[4];
        wmma::fragment<wmma::matrix_b, 16, 16, 16, __nv_bfloat16, wmma::row_major> bf[4];
#pragma unroll
        for (int i = 0; i < 4; i++)
            wmma::load_matrix_sync(af[i], &As[buf][(wr * 64 + i * 16) * LDA], LDA);
#pragma unroll
        for (int j = 0; j < 4; j++)
            wmma::load_matrix_sync(bf[j], &Bs[buf][wc * 64 + j * 16], LDB);
#pragma unroll
        for (int i = 0; i < 4; i++)
#pragma unroll
            for (int j = 0; j < 4; j++)
                wmma::mma_sync(acc[i][j], af[i], bf[j], acc[i][j]);

        if (c < 31) {
#pragma unroll
            for (int h = 0; h < 2; h++) {
                const int u = t + 128 * h;
                *(uint4*)(&As[buf ^ 1][(u >> 1) * LDA + (u & 1) * 8]) = ea[h];
            }
#pragma unroll
            for (int p = 0; p < 4; p++) {
                const int u = t + 128 * p;
                const int r = u >> 5;
                const float zi = zs[kk1 + r];
                float4 v = rv[p];
                v.x *= zi; v.y *= zi; v.z *= zi; v.w *= zi;
                *(uint2*)(&Bs[buf ^ 1][r * LDB + (u & 31) * 4]) = pack4(v);
            }
        }
        __syncthreads();
    }

    // store accumulators straight to gmem (ldm = 512, multiple of 4)
    float* Ob = O + ((size_t)batch * SD + it * 128) * SD + jt * 128;
#pragma unroll
    for (int i = 0; i < 4; i++)
#pragma unroll
        for (int j = 0; j < 4; j++)
            wmma::store_matrix_sync(Ob + (size_t)(wr * 64 + i * 16) * SD + wc * 64 + j * 16,
                                    acc[i][j], SD, wmma::mem_row_major);
}

// ---------------------------------------------------------------------------
extern "C" void kernel_launch(void* const* d_in, const int* in_sizes, int n_in,
                              void* d_out, int out_size)
{
    (void)in_sizes; (void)n_in; (void)out_size;
    const float* Q = (const float*)d_in[1];
    const float* K = (const float*)d_in[2];
    const float* V = (const float*)d_in[3];
    float* out = (float*)d_out;

    cudaFuncSetAttribute(k1_qk, cudaFuncAttributeMaxDynamicSharedMemorySize, K1_SMEM);

    dim3 g(16, NB);
    k1_qk<<<g, 128, K1_SMEM>>>(Q, K);
    k_zred<<<NB, 512>>>();
    k2_pv<<<g, 128>>>(V, out);
}

// round 6
// speedup vs baseline: 1.2453x; 1.2453x over previous
#include <cuda_runtime.h>
#include <cuda_bf16.h>
#include <mma.h>
#include <cstdint>

using namespace nvcuda;

#define SD 512
#define NB 512                 // QLEN(128) * HEADS(4)
#define SCALE 0.044194173824159216f

#define BM 128
#define BN 128
#define BK 32
#define LDA 40      // smem stride (bf16) for 128x32 tiles (80B rows)
#define LDC 132     // smem stride (fp32) for 128x128 staging tile
#define LDB2 136    // smem stride (bf16) for 32x128 V tile
#define K1_SMEM (BM * LDC * 4)   // 67584 bytes (tiles alias the staging)

// ---- scratch (device globals; no allocation) ----
__device__ __nv_bfloat16 g_E[(size_t)NB * SD * SD];   // exp(scale*QK^T), unnormalized
__device__ float g_partZ[NB][4][SD];
__device__ float g_Zinv[NB][SD];

__device__ __forceinline__ uint2 pack4(float4 v) {
    __nv_bfloat162 a = __float22bfloat162_rn(make_float2(v.x, v.y));
    __nv_bfloat162 b = __float22bfloat162_rn(make_float2(v.z, v.w));
    uint2 u;
    u.x = *(uint32_t*)&a;
    u.y = *(uint32_t*)&b;
    return u;
}

// ---------------------------------------------------------------------------
// k1: S = Q K^T (bf16 HMMA, fp32 acc); exp in regs; E -> gmem; col partials.
// 256 threads = 8 warps (4 row-groups x 2 col-groups), warp tile 32x64.
// grid (16, 512): blockIdx.x = it*4 + nt. 2 CTAs/SM via launch_bounds.
// ---------------------------------------------------------------------------
__global__ void __launch_bounds__(256, 2) k1_qk(const float* __restrict__ Q,
                                                const float* __restrict__ Km)
{
    extern __shared__ char smem_raw[];
    __nv_bfloat16* As = (__nv_bfloat16*)smem_raw;        // [BM][LDA]
    __nv_bfloat16* Bs = As + BM * LDA;                   // [BN][LDA]
    float* Cs = (float*)smem_raw;                        // aliased post-mainloop

    const int batch = blockIdx.y;
    const int it = blockIdx.x >> 2;
    const int nt = blockIdx.x & 3;
    const float* Qb = Q  + ((size_t)batch * SD + it * BM) * SD;
    const float* Kb = Km + ((size_t)batch * SD + nt * BN) * SD;

    const int tid = threadIdx.x;
    const int wid = tid >> 5;
    const int wr = wid & 3;    // warp row group (32 rows)
    const int wc = wid >> 2;   // warp col group (64 cols)

    wmma::fragment<wmma::accumulator, 16, 16, 16, float> acc[2][4];
#pragma unroll
    for (int a = 0; a < 2; a++)
#pragma unroll
        for (int b = 0; b < 4; b++) wmma::fill_fragment(acc[a][b], 0.0f);

    const int lr = tid >> 3;          // 0..31
    const int lc = (tid & 7) << 2;    // 0,4,...,28

#pragma unroll 1
    for (int kk = 0; kk < SD; kk += BK) {
#pragma unroll
        for (int i = 0; i < 4; i++) {
            const int row = lr + (i << 5);
            float4 qa = *(const float4*)(Qb + (size_t)row * SD + kk + lc);
            float4 ka = *(const float4*)(Kb + (size_t)row * SD + kk + lc);
            *(uint2*)(As + row * LDA + lc) = pack4(qa);
            *(uint2*)(Bs + row * LDA + lc) = pack4(ka);
        }
        __syncthreads();
#pragma unroll
        for (int ks = 0; ks < BK; ks += 16) {
            wmma::fragment<wmma::matrix_a, 16, 16, 16, __nv_bfloat16, wmma::row_major> af[2];
            wmma::fragment<wmma::matrix_b, 16, 16, 16, __nv_bfloat16, wmma::col_major> bf[4];
#pragma unroll
            for (int a = 0; a < 2; a++)
                wmma::load_matrix_sync(af[a], As + (wr * 32 + a * 16) * LDA + ks, LDA);
#pragma unroll
            for (int b = 0; b < 4; b++)
                wmma::load_matrix_sync(bf[b], Bs + (wc * 64 + b * 16) * LDA + ks, LDA);
#pragma unroll
            for (int a = 0; a < 2; a++)
#pragma unroll
                for (int b = 0; b < 4; b++)
                    wmma::mma_sync(acc[a][b], af[a], bf[b], acc[a][b]);
        }
        __syncthreads();
    }

    // exp in registers (elementwise on accumulators — layout independent)
#pragma unroll
    for (int a = 0; a < 2; a++)
#pragma unroll
        for (int b = 0; b < 4; b++)
#pragma unroll
            for (int e = 0; e < acc[a][b].num_elements; e++)
                acc[a][b].x[e] = __expf(acc[a][b].x[e] * SCALE);

    // stage exp'd tile to smem (aliases As/Bs; all tile reads complete)
#pragma unroll
    for (int a = 0; a < 2; a++)
#pragma unroll
        for (int b = 0; b < 4; b++)
            wmma::store_matrix_sync(Cs + (wr * 32 + a * 16) * LDC + wc * 64 + b * 16,
                                    acc[a][b], LDC, wmma::mem_row_major);
    __syncthreads();

    // deterministic column partial sums: 2 threads per column, fixed order
    {
        const int col = tid & 127, half = tid >> 7;
        float zsum = 0.f;
#pragma unroll 8
        for (int r = half * 64; r < half * 64 + 64; r++)
            zsum += Cs[r * LDC + col];
        __shared__ float zs[256];
        zs[half * 128 + col] = zsum;
        __syncthreads();
        if (tid < 128)
            g_partZ[batch][it][nt * BN + tid] = zs[tid] + zs[128 + tid];
    }

    // coalesced E store (bf16): 2 threads per row, 64 cols each
    __nv_bfloat16* Eb = g_E + ((size_t)batch * SD + it * BM) * SD + nt * BN;
    {
        const int row = tid >> 1, c0 = (tid & 1) * 64;
        const float* src = Cs + row * LDC + c0;
#pragma unroll
        for (int i = 0; i < 8; i++) {
            uint2 lo = pack4(*(const float4*)(src + i * 8));
            uint2 hi = pack4(*(const float4*)(src + i * 8 + 4));
            uint4 o; o.x = lo.x; o.y = lo.y; o.z = hi.x; o.w = hi.y;
            *(uint4*)(Eb + (size_t)row * SD + c0 + i * 8) = o;
        }
    }
}

// ---------------------------------------------------------------------------
// k_zred: Z = fixed-order sum of 4 partials; store 1/Z
// ---------------------------------------------------------------------------
__global__ void __launch_bounds__(512) k_zred()
{
    const int b = blockIdx.x, c = threadIdx.x;
    float z = g_partZ[b][0][c] + g_partZ[b][1][c] + g_partZ[b][2][c] + g_partZ[b][3][c];
    g_Zinv[b][c] = 1.0f / z;
}

// ---------------------------------------------------------------------------
// k2: out = E @ (diag(1/Z) V). E bf16 scratch; V fp32 scaled by 1/Z_k at load.
// Same 8-warp layout; accumulators stored straight to gmem.
// ---------------------------------------------------------------------------
__global__ void __launch_bounds__(256, 2) k2_pv(const float* __restrict__ V,
                                                float* __restrict__ O)
{
    __shared__ __nv_bfloat16 As[BM * LDA];    // E tile 128 x 32
    __shared__ __nv_bfloat16 Bs[BK * LDB2];   // scaled V tile 32 x 128
    __shared__ float zs[SD];

    const int batch = blockIdx.y, it = blockIdx.x >> 2, jt = blockIdx.x & 3;
    const __nv_bfloat16* Eb = g_E + ((size_t)batch * SD + it * BM) * SD;
    const float* Vb = V + (size_t)batch * SD * SD + jt * BN;

    const int tid = threadIdx.x, wid = tid >> 5;
    const int wr = wid & 3, wc = wid >> 2;

    if (tid < 128) ((float4*)zs)[tid] = ((const float4*)g_Zinv[batch])[tid];

    wmma::fragment<wmma::accumulator, 16, 16, 16, float> acc[2][4];
#pragma unroll
    for (int a = 0; a < 2; a++)
#pragma unroll
        for (int b = 0; b < 4; b++) wmma::fill_fragment(acc[a][b], 0.0f);
    __syncthreads();   // zs visible

#pragma unroll 1
    for (int kk = 0; kk < SD; kk += BK) {
        // E tile: 128 rows x 32 bf16 (uint4 = 8 bf16)
#pragma unroll
        for (int i = 0; i < 2; i++) {
            const int row = (tid >> 2) + i * 64;
            const int c8 = (tid & 3) * 8;
            *(uint4*)(As + row * LDA + c8) =
                *(const uint4*)(Eb + (size_t)row * SD + kk + c8);
        }
        // V tile: 32 k-rows x 128 j-cols fp32, scaled by zinv[k] -> bf16
        {
            const int k = tid >> 3;
            const float zi = zs[kk + k];
#pragma unroll
            for (int i = 0; i < 2; i++) {
                const int j = ((tid & 7) + i * 8) * 8;
                float4 v0 = *(const float4*)(Vb + (size_t)(kk + k) * SD + j);
                float4 v1 = *(const float4*)(Vb + (size_t)(kk + k) * SD + j + 4);
                v0.x *= zi; v0.y *= zi; v0.z *= zi; v0.w *= zi;
                v1.x *= zi; v1.y *= zi; v1.z *= zi; v1.w *= zi;
                uint2 lo = pack4(v0), hi = pack4(v1);
                uint4 o; o.x = lo.x; o.y = lo.y; o.z = hi.x; o.w = hi.y;
                *(uint4*)(Bs + k * LDB2 + j) = o;
            }
        }
        __syncthreads();
#pragma unroll
        for (int ks = 0; ks < BK; ks += 16) {
            wmma::fragment<wmma::matrix_a, 16, 16, 16, __nv_bfloat16, wmma::row_major> af[2];
            wmma::fragment<wmma::matrix_b, 16, 16, 16, __nv_bfloat16, wmma::row_major> bf[4];
#pragma unroll
            for (int a = 0; a < 2; a++)
                wmma::load_matrix_sync(af[a], As + (wr * 32 + a * 16) * LDA + ks, LDA);
#pragma unroll
            for (int b = 0; b < 4; b++)
                wmma::load_matrix_sync(bf[b], Bs + ks * LDB2 + wc * 64 + b * 16, LDB2);
#pragma unroll
            for (int a = 0; a < 2; a++)
#pragma unroll
                for (int b = 0; b < 4; b++)
                    wmma::mma_sync(acc[a][b], af[a], bf[b], acc[a][b]);
        }
        __syncthreads();
    }

    float* Ob = O + ((size_t)batch * SD + it * BM) * SD + jt * BN;
#pragma unroll
    for (int a = 0; a < 2; a++)
#pragma unroll
        for (int b = 0; b < 4; b++)
            wmma::store_matrix_sync(Ob + (size_t)(wr * 32 + a * 16) * SD + wc * 64 + b * 16,
                                    acc[a][b], SD, wmma::mem_row_major);
}

// ---------------------------------------------------------------------------
extern "C" void kernel_launch(void* const* d_in, const int* in_sizes, int n_in,
                              void* d_out, int out_size)
{
    (void)in_sizes; (void)n_in; (void)out_size;
    const float* Q = (const float*)d_in[1];
    const float* K = (const float*)d_in[2];
    const float* V = (const float*)d_in[3];
    float* out = (float*)d_out;

    cudaFuncSetAttribute(k1_qk, cudaFuncAttributeMaxDynamicSharedMemorySize, K1_SMEM);

    dim3 g(16, NB);
    k1_qk<<<g, 256, K1_SMEM>>>(Q, K);
    k_zred<<<NB, 512>>>();
    k2_pv<<<g, 256>>>(V, out);
}